// round 13
// baseline (speedup 1.0000x reference)
#include <cuda_runtime.h>
#include <cuda_bf16.h>

#define BATCH 512
#define NTOK  4096
#define NP1   4097
#define NTHR  512

#define CONTENT_PAD 1024.0f
#define CONTENT_EOS 1025.0f

// Copy cnt elems from two smem arrays (bases phase-matched to gmem alignment)
// to two gmem planes. 128-bit on both sides in the bulk.
__device__ __forceinline__ void copy_pair(float* __restrict__ pc, float* __restrict__ pp,
                                          const float* __restrict__ svb,
                                          const float* __restrict__ spb,
                                          int cnt, int t, int b_align)
{
    int vs = (4 - b_align) & 3;
    if (vs > cnt) vs = cnt;
    for (int j = t; j < vs; j += NTHR) { pc[j] = svb[j]; pp[j] = spb[j]; }
    const int nvec = (cnt - vs) >> 2;
    const float4* s4 = (const float4*)(svb + vs);
    const float4* q4 = (const float4*)(spb + vs);
    float4* c4 = (float4*)(pc + vs);
    float4* p4 = (float4*)(pp + vs);
    for (int c = t; c < nvec; c += NTHR) {
        c4[c] = s4[c];
        p4[c] = q4[c];
    }
    for (int j = vs + (nvec << 2) + t; j < cnt; j += NTHR) {
        pc[j] = svb[j]; pp[j] = spb[j];
    }
}

// EOS at cnt, PAD beyond, two planes sharing cnt.
__device__ __forceinline__ void tail_pair(float* __restrict__ pc, float* __restrict__ pp,
                                          int cnt, float eosC, float padC,
                                          float eosP, float padP,
                                          int t, int b_align)
{
    if (t == 0) { pc[cnt] = eosC; pp[cnt] = eosP; }
    const int start = cnt + 1;
    int vs = start + ((4 - ((start + b_align) & 3)) & 3);
    if (vs > NP1) vs = NP1;
    for (int j = start + t; j < vs; j += NTHR) { pc[j] = padC; pp[j] = padP; }
    const int nvec = (NP1 - vs) >> 2;
    float4* c4 = (float4*)(pc + vs);
    float4* p4 = (float4*)(pp + vs);
    const float4 pcv = make_float4(padC, padC, padC, padC);
    const float4 ppv = make_float4(padP, padP, padP, padP);
    for (int c = t; c < nvec; c += NTHR) { c4[c] = pcv; p4[c] = ppv; }
    for (int j = vs + (nvec << 2) + t; j < NP1; j += NTHR) {
        pc[j] = padC; pp[j] = padP;
    }
}

// Three constant planes in one loop.
__device__ __forceinline__ void fill_const3(float* __restrict__ p0, float* __restrict__ p1,
                                            float* __restrict__ p2,
                                            int t, int b_align)
{
    const int vs = (4 - b_align) & 3;
    for (int j = t; j < vs; j += NTHR) { p0[j] = 0.0f; p1[j] = 1.0f; p2[j] = 2.0f; }
    const int nvec = (NP1 - vs) >> 2;
    float4* a4 = (float4*)(p0 + vs);
    float4* b4 = (float4*)(p1 + vs);
    float4* c4 = (float4*)(p2 + vs);
    const float4 v0 = make_float4(0.f, 0.f, 0.f, 0.f);
    const float4 v1 = make_float4(1.f, 1.f, 1.f, 1.f);
    const float4 v2 = make_float4(2.f, 2.f, 2.f, 2.f);
    for (int c = t; c < nvec; c += NTHR) { a4[c] = v0; b4[c] = v1; c4[c] = v2; }
    const int tail = vs + (nvec << 2);
    for (int j = tail + t; j < NP1; j += NTHR) { p0[j] = 0.0f; p1[j] = 1.0f; p2[j] = 2.0f; }
}

// Output: 9 sections, each [BATCH, NP1] float32, tuple order:
//  0 coarse_content, 1 medium_content, 2 fine_content,
//  3 coarse_position, 4 medium_position, 5 fine_position,
//  6 coarse_segment,  7 medium_segment,  8 fine_segment
// Grid: (BATCH, 4). y=0/1/2 handle class y's content+position planes;
// y=3 handles the three constant segment planes.
__global__ __launch_bounds__(NTHR)
void triple_grain_kernel(const int* __restrict__ in0,
                         const int* __restrict__ in1,
                         float* __restrict__ out)
{
    const int b = blockIdx.x;
    const int y = blockIdx.y;
    const int t = threadIdx.x;
    const int b_align = b & 3;          // 4097*b mod 4 == b mod 4
    const long plane = (long)BATCH * NP1;
    const long rowb  = (long)b * NP1;

    if (y == 3) {
        // pure constant fills, no loads / sync / smem
        fill_const3(out + 6 * plane + rowb,
                    out + 7 * plane + rowb,
                    out + 8 * plane + rowb, t, b_align);
        return;
    }

    __shared__ __align__(16) float sval[NTOK + 4];
    __shared__ __align__(16) float sposn[NTOK + 4];

    const unsigned lane = t & 31u;
    const unsigned warp = t >> 5;

    const int4* a4 = (const int4*)(in0 + (long)b * NTOK);
    const int4* b4 = (const int4*)(in1 + (long)b * NTOK);

    // ---- phase 1: load, max(in0) + counts for BOTH interpretations ----
    unsigned a0 = 0, a1 = 0, b0c = 0, b1c = 0;
    int amax = 0;
    {
        int4 xa = a4[t * 2 + 0];
        int4 xb = a4[t * 2 + 1];
        int4 ya = b4[t * 2 + 0];
        int4 yb = b4[t * 2 + 1];
        int av[8] = {xa.x, xa.y, xa.z, xa.w, xb.x, xb.y, xb.z, xb.w};
        int bv[8] = {ya.x, ya.y, ya.z, ya.w, yb.x, yb.y, yb.z, yb.w};
#pragma unroll
        for (int i = 0; i < 8; i++) {
            amax = max(amax, av[i]);
            a0 += (av[i] == 0); a1 += (av[i] == 1);
            b0c += (bv[i] == 0); b1c += (bv[i] == 1);
        }
    }
#pragma unroll
    for (int d = 16; d > 0; d >>= 1)
        amax = max(amax, __shfl_xor_sync(0xffffffffu, amax, d));

    __shared__ int smax[16];
    __shared__ int s_a_is_grain;
    if (lane == 0) smax[warp] = amax;
    __syncthreads();
    if (t == 0) {
        int m = smax[0];
#pragma unroll
        for (int i = 1; i < 16; i++) m = max(m, smax[i]);
        s_a_is_grain = (m <= 2) ? 1 : 0;
    }
    __syncthreads();
    const bool a_is_grain = (s_a_is_grain != 0);

    const unsigned packed = a_is_grain ? (a0 | (a1 << 16)) : (b0c | (b1c << 16));

    // ---- block-wide exclusive scan of packed (16 warps) ----
    unsigned inc = packed;
#pragma unroll
    for (int d = 1; d < 32; d <<= 1) {
        unsigned n = __shfl_up_sync(0xffffffffu, inc, d);
        if (lane >= (unsigned)d) inc += n;
    }

    __shared__ unsigned warp_sums[16];
    __shared__ unsigned block_total;
    if (lane == 31) warp_sums[warp] = inc;
    __syncthreads();

    if (warp == 0 && lane < 16) {
        unsigned w = warp_sums[lane];
        unsigned wi = w;
#pragma unroll
        for (int d = 1; d < 16; d <<= 1) {
            unsigned n = __shfl_up_sync(0xffffu, wi, d);
            if (lane >= (unsigned)d) wi += n;
        }
        warp_sums[lane] = wi - w;
        if (lane == 15) block_total = wi;
    }
    __syncthreads();

    const unsigned ex = warp_sums[warp] + (inc - packed);
    const unsigned tot = block_total;

    const int cnt0 = (int)(tot & 0xFFFFu);
    const int cnt1 = (int)(tot >> 16);
    const int ex0 = (int)(ex & 0xFFFFu);
    const int ex1 = (int)(ex >> 16);

    // this block's class parameters
    int cnt, off;
    if (y == 0)      { cnt = cnt0;                 off = ex0; }
    else if (y == 1) { cnt = cnt1;                 off = ex1; }
    else             { cnt = NTOK - cnt0 - cnt1;   off = 8 * t - ex0 - ex1; }
    off += b_align;                       // smem base phase-matched to gmem

    const float posEOS = (y == 0) ? 129.0f : (y == 1) ? 257.0f : 1025.0f;
    const float posPAD = (y == 0) ? 128.0f : (y == 1) ? 256.0f : 1024.0f;

    // ---- phase 2: reload inputs (L1/L2-hot), scatter ONLY class y ----
    {
        int4 xa = a4[t * 2 + 0];
        int4 xb = a4[t * 2 + 1];
        int4 ya = b4[t * 2 + 0];
        int4 yb = b4[t * 2 + 1];
        int av[8] = {xa.x, xa.y, xa.z, xa.w, xb.x, xb.y, xb.z, xb.w};
        int bv[8] = {ya.x, ya.y, ya.z, ya.w, yb.x, yb.y, yb.z, yb.w};
        const int pbase = t * 8;
#pragma unroll
        for (int i = 0; i < 8; i++) {
            const int g = a_is_grain ? av[i] : bv[i];
            const int v = a_is_grain ? bv[i] : av[i];
            if (g == y) {
                sval[off]  = (float)v;
                sposn[off] = (float)(pbase + i);
                off++;
            }
        }
    }
    __syncthreads();

    float* pc = out + (0 + y) * plane + rowb;   // content plane for class y
    float* pp = out + (3 + y) * plane + rowb;   // position plane for class y

    copy_pair(pc, pp, sval + b_align, sposn + b_align, cnt, t, b_align);
    tail_pair(pc, pp, cnt, CONTENT_EOS, CONTENT_PAD, posEOS, posPAD, t, b_align);
}

extern "C" void kernel_launch(void* const* d_in, const int* in_sizes, int n_in,
                              void* d_out, int out_size)
{
    const int* in0 = (const int*)d_in[0];
    const int* in1 = (const int*)d_in[1];
    float* out = (float*)d_out;
    triple_grain_kernel<<<dim3(BATCH, 4), NTHR>>>(in0, in1, out);
}

// round 16
// speedup vs baseline: 1.4034x; 1.4034x over previous
#include <cuda_runtime.h>
#include <cuda_bf16.h>

#define BATCH 512
#define NTOK  4096
#define NP1   4097
#define NTHR  512

#define CONTENT_PAD 1024.0f
#define CONTENT_EOS 1025.0f
#define COARSE_POS_PAD 128.0f
#define COARSE_POS_EOS 129.0f
#define MEDIUM_POS_PAD 256.0f
#define MEDIUM_POS_EOS 257.0f
#define FINE_POS_PAD 1024.0f
#define FINE_POS_EOS 1025.0f

// Copy cnt elems from interleaved (val,pos) smem pairs to two gmem planes.
// basei+vs is even so the bulk reads are LDS.128 (two pairs per load).
__device__ __forceinline__ void copy_pair(float* __restrict__ pc, float* __restrict__ pp,
                                          const float2* __restrict__ sp,   // element j at sp[j]
                                          int cnt, int t, int b_align)
{
    int vs = (4 - b_align) & 3;
    if (vs > cnt) vs = cnt;
    for (int j = t; j < vs; j += NTHR) { float2 e = sp[j]; pc[j] = e.x; pp[j] = e.y; }
    const int nvec = (cnt - vs) >> 2;
    const float4* s4 = (const float4*)(sp + vs);     // 16B-aligned by base parity
    float4* c4 = (float4*)(pc + vs);
    float4* p4 = (float4*)(pp + vs);
    for (int c = t; c < nvec; c += NTHR) {
        float4 f0 = s4[2 * c + 0];                   // (v0,p0,v1,p1)
        float4 f1 = s4[2 * c + 1];                   // (v2,p2,v3,p3)
        c4[c] = make_float4(f0.x, f0.z, f1.x, f1.z);
        p4[c] = make_float4(f0.y, f0.w, f1.y, f1.w);
    }
    for (int j = vs + (nvec << 2) + t; j < cnt; j += NTHR) {
        float2 e = sp[j]; pc[j] = e.x; pp[j] = e.y;
    }
}

// EOS at cnt, PAD beyond, two planes sharing cnt.
__device__ __forceinline__ void tail_pair(float* __restrict__ pc, float* __restrict__ pp,
                                          int cnt, float eosC, float padC,
                                          float eosP, float padP,
                                          int t, int b_align)
{
    if (t == 0) { pc[cnt] = eosC; pp[cnt] = eosP; }
    const int start = cnt + 1;
    int vs = start + ((4 - ((start + b_align) & 3)) & 3);
    if (vs > NP1) vs = NP1;
    for (int j = start + t; j < vs; j += NTHR) { pc[j] = padC; pp[j] = padP; }
    const int nvec = (NP1 - vs) >> 2;
    float4* c4 = (float4*)(pc + vs);
    float4* p4 = (float4*)(pp + vs);
    const float4 pcv = make_float4(padC, padC, padC, padC);
    const float4 ppv = make_float4(padP, padP, padP, padP);
    for (int c = t; c < nvec; c += NTHR) { c4[c] = pcv; p4[c] = ppv; }
    for (int j = vs + (nvec << 2) + t; j < NP1; j += NTHR) {
        pc[j] = padC; pp[j] = padP;
    }
}

// Three constant planes in one loop.
__device__ __forceinline__ void fill_const3(float* __restrict__ p0, float* __restrict__ p1,
                                            float* __restrict__ p2,
                                            int t, int b_align)
{
    const int vs = (4 - b_align) & 3;
    for (int j = t; j < vs; j += NTHR) { p0[j] = 0.0f; p1[j] = 1.0f; p2[j] = 2.0f; }
    const int nvec = (NP1 - vs) >> 2;
    float4* a4 = (float4*)(p0 + vs);
    float4* b4 = (float4*)(p1 + vs);
    float4* c4 = (float4*)(p2 + vs);
    const float4 v0 = make_float4(0.f, 0.f, 0.f, 0.f);
    const float4 v1 = make_float4(1.f, 1.f, 1.f, 1.f);
    const float4 v2 = make_float4(2.f, 2.f, 2.f, 2.f);
    for (int c = t; c < nvec; c += NTHR) { a4[c] = v0; b4[c] = v1; c4[c] = v2; }
    const int tail = vs + (nvec << 2);
    for (int j = tail + t; j < NP1; j += NTHR) { p0[j] = 0.0f; p1[j] = 1.0f; p2[j] = 2.0f; }
}

// Output: 9 sections, each [BATCH, NP1] float32, tuple order:
//  0 coarse_content, 1 medium_content, 2 fine_content,
//  3 coarse_position, 4 medium_position, 5 fine_position,
//  6 coarse_segment,  7 medium_segment,  8 fine_segment
__global__ __launch_bounds__(NTHR)
void triple_grain_kernel(const int* __restrict__ in0,
                         const int* __restrict__ in1,
                         float* __restrict__ out)
{
    __shared__ __align__(16) float2 spair[NTOK + 8];   // interleaved (val,pos)
    __shared__ unsigned warp_sums[16];
    __shared__ unsigned block_total;

    const int b = blockIdx.x;
    const int t = threadIdx.x;
    const unsigned lane = t & 31u;
    const unsigned warp = t >> 5;
    const int b_align = b & 3;              // 4097*b mod 4 == b mod 4

    const long plane = (long)BATCH * NP1;
    const long rowb  = (long)b * NP1;

    const int4* a4 = (const int4*)(in0 + (long)b * NTOK);
    const int4* b4 = (const int4*)(in1 + (long)b * NTOK);

    // ---- phase 1 loads issued first ----
    int4 xa = a4[t * 2 + 0];
    int4 xb = a4[t * 2 + 1];
    int4 ya = b4[t * 2 + 0];
    int4 yb = b4[t * 2 + 1];

    // ---- constant segment planes: pure stores, drain in the LDG shadow ----
    fill_const3(out + 6 * plane + rowb,
                out + 7 * plane + rowb,
                out + 8 * plane + rowb, t, b_align);

    int av[8] = {xa.x, xa.y, xa.z, xa.w, xb.x, xb.y, xb.z, xb.w};
    int bv[8] = {ya.x, ya.y, ya.z, ya.w, yb.x, yb.y, yb.z, yb.w};

    // ---- which input is grain? (values <= 2) — one fused barrier+OR ----
    int amax = av[0];
#pragma unroll
    for (int i = 1; i < 8; i++) amax = max(amax, av[i]);
    const bool a_is_grain = (__syncthreads_or(amax > 2) == 0);

    // ---- counts on selected side only ----
    unsigned c0 = 0, c1 = 0;
#pragma unroll
    for (int i = 0; i < 8; i++) {
        const int g = a_is_grain ? av[i] : bv[i];
        c0 += (g == 0);
        c1 += (g == 1);
    }
    const unsigned packed = c0 | (c1 << 16);

    // ---- block-wide exclusive scan of packed (16 warps) ----
    unsigned inc = packed;
#pragma unroll
    for (int d = 1; d < 32; d <<= 1) {
        unsigned n = __shfl_up_sync(0xffffffffu, inc, d);
        if (lane >= (unsigned)d) inc += n;
    }
    if (lane == 31) warp_sums[warp] = inc;
    __syncthreads();
    if (warp == 0 && lane < 16) {
        unsigned w = warp_sums[lane];
        unsigned wi = w;
#pragma unroll
        for (int d = 1; d < 16; d <<= 1) {
            unsigned n = __shfl_up_sync(0xffffu, wi, d);
            if (lane >= (unsigned)d) wi += n;
        }
        warp_sums[lane] = wi - w;
        if (lane == 15) block_total = wi;
    }
    __syncthreads();

    const unsigned ex = warp_sums[warp] + (inc - packed);
    const unsigned tot = block_total;

    const int cnt0 = (int)(tot & 0xFFFFu);
    const int cnt1 = (int)(tot >> 16);
    const int cnt2 = NTOK - cnt0 - cnt1;

    // per-class smem bases: parity == vs parity so LDS.128 at element vs aligns
    const int par = ((4 - b_align) & 3) & 1;
    const int base0 = par;
    const int base1 = (((base0 + cnt0 + 1) & ~1)) + par;
    const int base2 = (((base1 + cnt1 + 1) & ~1)) + par;

    int off0 = base0 + (int)(ex & 0xFFFFu);
    int off1 = base1 + (int)(ex >> 16);
    int off2 = base2 + (8 * t - (int)(ex & 0xFFFFu) - (int)(ex >> 16));

    // ---- phase 2: reload inputs (L1-hot) and scatter interleaved pairs ----
    {
        int4 ra = a4[t * 2 + 0];
        int4 rb = a4[t * 2 + 1];
        int4 sa = b4[t * 2 + 0];
        int4 sb = b4[t * 2 + 1];
        int gva[8] = {ra.x, ra.y, ra.z, ra.w, rb.x, rb.y, rb.z, rb.w};
        int gvb[8] = {sa.x, sa.y, sa.z, sa.w, sb.x, sb.y, sb.z, sb.w};
        const int pbase = t * 8;
#pragma unroll
        for (int i = 0; i < 8; i++) {
            const int g = a_is_grain ? gva[i] : gvb[i];
            const int v = a_is_grain ? gvb[i] : gva[i];
            int slot;
            if (g == 0)      { slot = off0++; }
            else if (g == 1) { slot = off1++; }
            else             { slot = off2++; }
            spair[slot] = make_float2((float)v, (float)(pbase + i));
        }
    }
    __syncthreads();

    // ---- section base pointers ----
    float* cc  = out + 0 * plane + rowb;
    float* mc  = out + 1 * plane + rowb;
    float* fc  = out + 2 * plane + rowb;
    float* cp  = out + 3 * plane + rowb;
    float* mp  = out + 4 * plane + rowb;
    float* fp_ = out + 5 * plane + rowb;

    // ---- coalesced writes: de-interleaving LDS.128 -> STG.128 + tails ----
    copy_pair(cc,  cp,  spair + base0, cnt0, t, b_align);
    tail_pair(cc,  cp,  cnt0, CONTENT_EOS, CONTENT_PAD, COARSE_POS_EOS, COARSE_POS_PAD, t, b_align);
    copy_pair(mc,  mp,  spair + base1, cnt1, t, b_align);
    tail_pair(mc,  mp,  cnt1, CONTENT_EOS, CONTENT_PAD, MEDIUM_POS_EOS, MEDIUM_POS_PAD, t, b_align);
    copy_pair(fc,  fp_, spair + base2, cnt2, t, b_align);
    tail_pair(fc,  fp_, cnt2, CONTENT_EOS, CONTENT_PAD, FINE_POS_EOS,   FINE_POS_PAD,   t, b_align);
}

extern "C" void kernel_launch(void* const* d_in, const int* in_sizes, int n_in,
                              void* d_out, int out_size)
{
    const int* in0 = (const int*)d_in[0];
    const int* in1 = (const int*)d_in[1];
    float* out = (float*)d_out;
    triple_grain_kernel<<<BATCH, NTHR>>>(in0, in1, out);
}